// round 8
// baseline (speedup 1.0000x reference)
#include <cuda_runtime.h>
#include <cuda_bf16.h>

// S=4096, H=3, E=512, G=3334, F=1, res=0.03
// out = sum_{s,h,e} mask*(b_h + w_h*feat)  -  0.03 * sum_{s,h,g} exp(b_h + w_h*grid)
//
// Row-aligned + row-halved, float4 grid body:
//   12288 rows = 3 * 4096 pairs. 8192 warps; warp w -> pair p = w>>1
//   (rows 3p+0/1/2, h is a compile-time literal), half = w&1.
//   Grid row (3334 floats, 13336 B): odd rows are 8B-misaligned, so each row
//   is decomposed as [1 float2 peel/tail] + [833 aligned float4]. half0 owns
//   float4 k in [0,416) + the float2 extra (lane 0); half1 owns [416,832) +
//   the float4 at k=832 (lane 0).

#define S_DIM 4096
#define H_DIM 3
#define E_DIM 512
#define G_DIM 3334

constexpr int NBLK = 1024;
constexpr int NTHR = 256;

constexpr int EV_ROW4 = E_DIM / 4;            // 128 float4 per event row

__device__ float g_part_log[NBLK];
__device__ float g_part_int[NBLK];
__device__ unsigned int g_done_count = 0;

__global__ void __launch_bounds__(NTHR, 8) lm_fused_kernel(
    const float* __restrict__ ev_feat,
    const int* __restrict__ ev_mask,      // bool -> int32 in the harness
    const float* __restrict__ gr_feat,
    const float* __restrict__ weights,
    const float* __restrict__ bases,
    const float* __restrict__ effects,
    float* __restrict__ out)
{
    const int lane = threadIdx.x & 31;
    const int wid  = threadIdx.x >> 5;
    const int warp = blockIdx.x * (NTHR / 32) + wid;   // 0..8191
    const int pair = warp >> 1;                        // 0..4095
    const int half = warp & 1;                         // 0 or 1

    // Per-head constants
    float wv[3], bv[3], wl[3], bl[3];
    #pragma unroll
    for (int h = 0; h < 3; h++) {
        wv[h] = weights[h] * effects[h];
        bv[h] = bases[h];
        wl[h] = wv[h] * 1.4426950408889634f;   // fold log2(e) for exp2
        bl[h] = bv[h] * 1.4426950408889634f;
    }

    float plog = 0.0f;
    float pint0 = 0.0f;
    float pint1 = 0.0f;

    // ---- Event part: rows 3*pair + h, this warp's half (64 float4) ----
    {
        const int kbase = half * (EV_ROW4 / 2) + lane;   // 0/64 + lane
        #pragma unroll
        for (int h = 0; h < 3; h++) {
            const int row = 3 * pair + h;
            const float4* __restrict__ f4 = (const float4*)ev_feat + (size_t)row * EV_ROW4;
            const int4*   __restrict__ m4 = (const int4*)ev_mask + (size_t)row * EV_ROW4;
            int   cnt = 0;
            float sum = 0.0f;
            #pragma unroll
            for (int i = 0; i < 2; i++) {
                const int k = kbase + 32 * i;
                const float4 f = f4[k];
                const int4   m = m4[k];
                if (m.x) { cnt++; sum += f.x; }
                if (m.y) { cnt++; sum += f.y; }
                if (m.z) { cnt++; sum += f.z; }
                if (m.w) { cnt++; sum += f.w; }
            }
            plog += fmaf(bv[h], (float)cnt, wv[h] * sum);
        }
    }

    // ---- Grid part: rows 3*pair + h, float4 body + float2 extra ----
    {
        const int kbase = half * 416 + lane;
        #pragma unroll
        for (int h = 0; h < 3; h++) {
            const int row = 3 * pair + h;
            const float* __restrict__ rbase = gr_feat + (size_t)row * G_DIM;
            const int odd = row & 1;
            const float4* __restrict__ g4 = (const float4*)(rbase + 2 * odd);  // 16B-aligned
            const float ww = wl[h];
            const float bb = bl[h];
            #pragma unroll 4
            for (int i = 0; i < 13; i++) {
                const float4 g = g4[kbase + 32 * i];
                pint0 += exp2f(fmaf(ww, g.x, bb));
                pint1 += exp2f(fmaf(ww, g.y, bb));
                pint0 += exp2f(fmaf(ww, g.z, bb));
                pint1 += exp2f(fmaf(ww, g.w, bb));
            }
            if (lane == 0) {
                if (half == 1) {
                    const float4 g = g4[832];                 // last float4 of body
                    pint0 += exp2f(fmaf(ww, g.x, bb));
                    pint1 += exp2f(fmaf(ww, g.y, bb));
                    pint0 += exp2f(fmaf(ww, g.z, bb));
                    pint1 += exp2f(fmaf(ww, g.w, bb));
                } else {
                    // extra float2: peel (odd rows, floats 0..1) or tail (even rows, 3332..3333)
                    const float2 e = *(const float2*)(odd ? rbase : rbase + (G_DIM - 2));
                    pint0 += exp2f(fmaf(ww, e.x, bb));
                    pint1 += exp2f(fmaf(ww, e.y, bb));
                }
            }
        }
    }

    float pint = pint0 + pint1;

    // ---- Block reduction ----
    __shared__ float s_log[NTHR / 32];
    __shared__ float s_int[NTHR / 32];
    __shared__ bool s_is_last;
    #pragma unroll
    for (int off = 16; off > 0; off >>= 1) {
        plog += __shfl_xor_sync(0xFFFFFFFFu, plog, off);
        pint += __shfl_xor_sync(0xFFFFFFFFu, pint, off);
    }
    if (lane == 0) { s_log[wid] = plog; s_int[wid] = pint; }
    __syncthreads();
    if (wid == 0) {
        float vl = (lane < NTHR / 32) ? s_log[lane] : 0.0f;
        float vi = (lane < NTHR / 32) ? s_int[lane] : 0.0f;
        #pragma unroll
        for (int off = 4; off > 0; off >>= 1) {
            vl += __shfl_xor_sync(0xFFFFFFFFu, vl, off);
            vi += __shfl_xor_sync(0xFFFFFFFFu, vi, off);
        }
        if (lane == 0) {
            g_part_log[blockIdx.x] = vl;
            g_part_int[blockIdx.x] = vi;
            __threadfence();
            unsigned int ticket = atomicAdd(&g_done_count, 1u);
            s_is_last = (ticket == (unsigned int)(NBLK - 1));
        }
    }
    __syncthreads();

    // ---- Last block: deterministic final combine in double ----
    if (s_is_last) {
        __shared__ double d_log[NTHR / 32];
        __shared__ double d_int[NTHR / 32];
        double dl = 0.0, di = 0.0;
        for (int j = threadIdx.x; j < NBLK; j += NTHR) {
            dl += (double)g_part_log[j];
            di += (double)g_part_int[j];
        }
        #pragma unroll
        for (int off = 16; off > 0; off >>= 1) {
            dl += __shfl_xor_sync(0xFFFFFFFFu, dl, off);
            di += __shfl_xor_sync(0xFFFFFFFFu, di, off);
        }
        if (lane == 0) { d_log[wid] = dl; d_int[wid] = di; }
        __syncthreads();
        if (threadIdx.x == 0) {
            double tl = 0.0, ti = 0.0;
            #pragma unroll
            for (int k = 0; k < NTHR / 32; k++) { tl += d_log[k]; ti += d_int[k]; }
            out[0] = (float)(tl - 0.03 * ti);
            g_done_count = 0;   // reset for next graph replay
        }
    }
}

extern "C" void kernel_launch(void* const* d_in, const int* in_sizes, int n_in,
                              void* d_out, int out_size)
{
    const float* ev_feat = (const float*)d_in[0];
    const int*   ev_mask = (const int*)d_in[1];
    const float* gr_feat = (const float*)d_in[2];
    const float* weights = (const float*)d_in[3];
    const float* bases   = (const float*)d_in[4];
    const float* effects = (const float*)d_in[5];
    float* out = (float*)d_out;

    lm_fused_kernel<<<NBLK, NTHR>>>(ev_feat, ev_mask, gr_feat, weights, bases, effects, out);
}